// round 16
// baseline (speedup 1.0000x reference)
#include <cuda_runtime.h>
#include <cuda_bf16.h>
#include <cuda_fp16.h>
#include <cstdint>

#define NB   8
#define CIN  64
#define OUT  64
#define HH   128
#define WW   128
#define HW   (HH*WW)          // 16384
#define NPIX (NB*HW)          // 131072
#define KWSTRIDE 576
#define MAXENTRIES (NPIX * 24)

// -------- scratch (static __device__, no allocation) --------
__device__ int      g_count;
__device__ unsigned g_list[MAXENTRIES];         // overflow entries: pid<<5 | (kk*3+b)
__device__ float    g_wpack[3 * 9 * CIN * OUT]; // wpack[(b*9+kk)*4096 + c*64 + o]

// -------- smem layout for dense kernel (144B padded rows) ----
#define ROWB 144                   // 72 fp16 per row: 64 data + 8 pad
#define ROWE 72
#define SM_A    0
#define SM_B_H  (SM_A + 256 * ROWB)      // 36864
#define SM_AB_END (SM_B_H + 64 * ROWB)   // 46080
#define DS_STRIDE 132              // epilogue staging row stride (floats)
#define DS_FLOATS (OUT * DS_STRIDE)      // 8448 floats per image row
#define DS_BYTES  (2 * DS_FLOATS * 4)    // 67584
// list region must be disjoint from (A,B) during staging AND Ds during epilogue
#define SM_LCNT 67584
#define SM_LIST (SM_LCNT + 16)
#define LCAP    1024
#define SM_TOTAL (SM_LIST + LCAP * 4)    // 71696

// pre-converted dense B (w1 center taps), fp16, padded-row layout
__device__ __align__(16) __half g_bh[OUT * ROWE];

__device__ __forceinline__ uint32_t smem_u32(const void* p) {
    uint32_t a;
    asm("{ .reg .u64 t; cvta.to.shared.u64 t, %1; cvt.u32.u64 %0, t; }" : "=r"(a) : "l"(p));
    return a;
}
__device__ __forceinline__ void ldm_x4(uint32_t* r, uint32_t addr) {
    asm volatile("ldmatrix.sync.aligned.m8n8.x4.shared.b16 {%0,%1,%2,%3}, [%4];"
                 : "=r"(r[0]), "=r"(r[1]), "=r"(r[2]), "=r"(r[3]) : "r"(addr));
}
__device__ __forceinline__ void mma16816h(float* d, const uint32_t* a,
                                          uint32_t b0, uint32_t b1) {
    asm volatile(
        "mma.sync.aligned.m16n8k16.row.col.f32.f16.f16.f32 "
        "{%0,%1,%2,%3}, {%4,%5,%6,%7}, {%8,%9}, {%0,%1,%2,%3};"
        : "+f"(d[0]), "+f"(d[1]), "+f"(d[2]), "+f"(d[3])
        : "r"(a[0]), "r"(a[1]), "r"(a[2]), "r"(a[3]), "r"(b0), "r"(b1));
}

// ============================================================
// Kernel P: coalesced weight repack (PDL: triggers dense launch)
// ============================================================
__global__ void __launch_bounds__(128)
k_prep(const float* __restrict__ w0,
       const float* __restrict__ w1,
       const float* __restrict__ w2) {
#if __CUDA_ARCH__ >= 900
    cudaTriggerProgrammaticLaunchCompletion();
#endif
    if (blockIdx.x == 0 && threadIdx.x == 0) g_count = 0;

    const int tid = blockIdx.x * 128 + threadIdx.x;   // 0..27647
    const int b = tid / 9216;
    const int base = (tid % 9216) * 4;
    const float* wb = (b == 0) ? w0 : (b == 1) ? w1 : w2;

    const float4 v4 = *reinterpret_cast<const float4*>(wb + base);
    const float vv[4] = {v4.x, v4.y, v4.z, v4.w};

    #pragma unroll
    for (int j = 0; j < 4; ++j) {
        const int idx = base + j;                      // o*576 + c*9 + kk
        const float v = vv[j];
        const int o = idx / KWSTRIDE;
        const int rem = idx - o * KWSTRIDE;
        const int c = rem / 9;
        const int kk = rem - c * 9;
        g_wpack[(size_t)(b * 9 + kk) * (CIN * OUT) + c * OUT + o] = v;
        if (b == 1 && kk == 4)
            g_bh[o * ROWE + c] = __float2half_rn(v);
    }
}

// ============================================================
// Kernel A: FUSED dense (mma.sync fp16 single-precision-in,
// fp32 accum) + masks + corrections.
// Block = TWO image rows, 256 threads / 8 warps.
// D = Ah * Bh^T; error = fp16 rounding of A and B (~3e-4 << 1e-3)
// ============================================================
__global__ void __launch_bounds__(256, 2)
k_dense_masks(const float* __restrict__ x,
              const float* __restrict__ depth,
              const float* __restrict__ fx,
              float* __restrict__ out) {
    extern __shared__ char smem[];
    const uint32_t sb = smem_u32(smem);
    int* s_cnt = reinterpret_cast<int*>(smem + SM_LCNT);
    unsigned* slist = reinterpret_cast<unsigned*>(smem + SM_LIST);

    const int t = threadIdx.x;
    const int rg = t >> 7;
    const int tt = t & 127;
    const int wid = t >> 5, lane = t & 31;
    const int wl = wid & 3;
    const int n = blockIdx.x >> 6;
    const int hbase = (blockIdx.x & 63) << 1;
    const int h = hbase + rg;

    if (t == 0) *s_cnt = 0;

    // ---- stage A (pre-sync: only needs x). fp16, padded rows ----
    {
        const int q  = t & 63;           // pixel pair 0..63
        const int hf = (t >> 6) & 1;     // channel half
        const int rga = t >> 7;          // staging row
        const int px0 = q * 2;
        const float* xb = x + (size_t)n * CIN * HW +
                          (size_t)(hbase + rga) * WW + px0;
        char* a0 = smem + SM_A + (rga * 128 + px0) * ROWB;
        char* a1 = a0 + ROWB;

        #pragma unroll 8
        for (int c = hf * 32; c < hf * 32 + 32; c += 2) {
            const float2 f0 = *reinterpret_cast<const float2*>(xb + (size_t)c * HW);
            const float2 f1 = *reinterpret_cast<const float2*>(xb + (size_t)(c + 1) * HW);
            // pixel px0 channels (c,c+1); pixel px0+1 channels (c,c+1)
            *reinterpret_cast<__half2*>(a0 + c * 2) =
                __float22half2_rn(make_float2(f0.x, f1.x));
            *reinterpret_cast<__half2*>(a1 + c * 2) =
                __float22half2_rn(make_float2(f0.y, f1.y));
        }
    }

    // ---- wait for k_prep's outputs (g_bh, g_wpack, g_count=0) ----
#if __CUDA_ARCH__ >= 900
    cudaGridDependencySynchronize();
#endif

    // ---- stage B: coalesced uint4 copy of fp16 weights (9216B) ----
    {
        const uint4* sh = reinterpret_cast<const uint4*>(g_bh);
        uint4* dh = reinterpret_cast<uint4*>(smem + SM_B_H);
        dh[t]       = sh[t];
        dh[t + 256] = sh[t + 256];
        if (t < 64) dh[t + 512] = sh[t + 512];
    }
    __syncthreads();

    // ---- mask eval -> block-local list (overflow -> global) ----
    {
        const int w = tt;
        const float* drow = depth + (size_t)n * HW;
        const float ctr = drow[h * WW + w];
        const float grid = ctr / fx[n];
        const float half = 0.5f * grid;
        const float t0 = ctr + grid;
        const float t2 = ctr - grid;
        const unsigned pxloc = (unsigned)(rg * 128 + tt);
        const unsigned pid = (unsigned)(n * HW + h * WW + w);
        #pragma unroll
        for (int dy = -1; dy <= 1; ++dy) {
            #pragma unroll
            for (int dx = -1; dx <= 1; ++dx) {
                const int kk = (dy + 1) * 3 + (dx + 1);
                if (kk == 4) continue;  // center: dense / provably off
                const int hh = h + dy, ww2 = w + dx;
                if (hh < 0 || hh >= HH || ww2 < 0 || ww2 >= WW) continue;
                const float dv = drow[hh * WW + ww2];
                #pragma unroll
                for (int b = 0; b < 3; ++b) {
                    const float tgt = (b == 0) ? t0 : (b == 1) ? ctr : t2;
                    if (fabsf(dv - tgt) <= half) {
                        const int pos = atomicAdd(s_cnt, 1);
                        if (pos < LCAP) {
                            slist[pos] = (pxloc << 5) | (unsigned)(kk * 3 + b);
                        } else {
                            const int gp = atomicAdd(&g_count, 1);
                            g_list[gp] = (pid << 5) | (unsigned)(kk * 3 + b);
                        }
                    }
                }
            }
        }
    }
#if __CUDA_ARCH__ >= 900
    cudaTriggerProgrammaticLaunchCompletion();
#endif

    // ---- MMA: 64 HMMA per warp (4 kt x 4 ntp x 2 mt x 2) ----
    const int g = lane >> 2;
    const int tig = lane & 3;
    const int px0 = wl * 32;

    const int amat = lane >> 3, ar = lane & 7;
    const uint32_t a_off = (uint32_t)((rg * 128 + px0 + ((amat & 1) << 3) + ar) * ROWB +
                                      (((amat >> 1) << 3) * 2));
    const uint32_t b_off = (uint32_t)(((((amat >> 1) << 3) + ar) * ROWB) +
                                      ((amat & 1) << 4));

    float acc[2][8][4];
    #pragma unroll
    for (int mt = 0; mt < 2; ++mt)
        #pragma unroll
        for (int nt = 0; nt < 8; ++nt)
            #pragma unroll
            for (int j = 0; j < 4; ++j) acc[mt][nt][j] = 0.0f;

    #pragma unroll
    for (int kt = 0; kt < 4; ++kt) {
        uint32_t ah[2][4];
        ldm_x4(ah[0], sb + SM_A + a_off + kt * 32);
        ldm_x4(ah[1], sb + SM_A + a_off + kt * 32 + 16 * ROWB);
        #pragma unroll
        for (int ntp = 0; ntp < 4; ++ntp) {
            uint32_t bh[4];
            ldm_x4(bh, sb + SM_B_H + b_off + ntp * 16 * ROWB + kt * 32);
            #pragma unroll
            for (int mt = 0; mt < 2; ++mt) {
                mma16816h(acc[mt][2 * ntp],     ah[mt], bh[0], bh[1]);
                mma16816h(acc[mt][2 * ntp + 1], ah[mt], bh[2], bh[3]);
            }
        }
    }

    // ---- transpose acc into smem staging (reuses A/B region) ----
    __syncthreads();           // A/B dead; list complete
    float* Ds = reinterpret_cast<float*>(smem) + rg * DS_FLOATS;
    #pragma unroll
    for (int mt = 0; mt < 2; ++mt) {
        #pragma unroll
        for (int nt = 0; nt < 8; ++nt) {
            const int o = nt * 8 + 2 * tig;
            const int px = px0 + mt * 16 + g;
            Ds[o * DS_STRIDE + px]           = acc[mt][nt][0];
            Ds[(o + 1) * DS_STRIDE + px]     = acc[mt][nt][1];
            Ds[o * DS_STRIDE + px + 8]       = acc[mt][nt][2];
            Ds[(o + 1) * DS_STRIDE + px + 8] = acc[mt][nt][3];
        }
    }
    __syncthreads();

    // ---- corrections: warps process the local list into Ds ----
    {
        const int cnt = min(*s_cnt, LCAP);
        for (int i = wid; i < cnt; i += 8) {
            const unsigned e = slist[i];
            const unsigned pxloc = e >> 5;
            const int bit = (int)(e & 31u);
            const int kk = bit / 3;
            const int b  = bit % 3;
            const int dy = kk / 3 - 1, dx = kk % 3 - 1;
            const int rg2 = (int)(pxloc >> 7);
            const int tt2 = (int)(pxloc & 127u);
            const int h2 = hbase + rg2;

            const float* xp = x + (size_t)n * CIN * HW +
                              (size_t)(h2 + dy) * WW + (tt2 + dx);
            const float x0 = xp[(size_t)lane * HW];
            const float x1 = xp[(size_t)(lane + 32) * HW];

            const float2* wp = reinterpret_cast<const float2*>(
                g_wpack + (size_t)(b * 9 + kk) * (CIN * OUT)) + lane;

            float s0 = 0.0f, s1 = 0.0f;
            #pragma unroll
            for (int c = 0; c < 32; ++c) {
                const float xc = __shfl_sync(0xffffffffu, x0, c);
                const float2 wv = wp[c * 32];
                s0 = fmaf(wv.x, xc, s0);
                s1 = fmaf(wv.y, xc, s1);
            }
            #pragma unroll
            for (int c = 0; c < 32; ++c) {
                const float xc = __shfl_sync(0xffffffffu, x1, c);
                const float2 wv = wp[(c + 32) * 32];
                s0 = fmaf(wv.x, xc, s0);
                s1 = fmaf(wv.y, xc, s1);
            }

            float* Dt = reinterpret_cast<float*>(smem) + rg2 * DS_FLOATS + tt2;
            atomicAdd(&Dt[(2 * lane) * DS_STRIDE],     s0);
            atomicAdd(&Dt[(2 * lane + 1) * DS_STRIDE], s1);
        }
    }
    __syncthreads();

    // ---- single coalesced float4 store: dense + corrections ----
    {
        const int p4 = (tt & 31) * 4;
        const int oph = tt >> 5;              // 0..3
        float* op = out + (size_t)(n * OUT) * HW + (size_t)h * WW + p4;
        #pragma unroll 4
        for (int o = oph; o < OUT; o += 4) {
            const float4 v = *reinterpret_cast<const float4*>(&Ds[o * DS_STRIDE + p4]);
            *reinterpret_cast<float4*>(op + (size_t)o * HW) = v;
        }
    }
}

// ============================================================
// Kernel C: overflow corrections (expected count = 0).
// ============================================================
__global__ void __launch_bounds__(256)
k_correct(const float* __restrict__ x,
          float* __restrict__ out) {
#if __CUDA_ARCH__ >= 900
    cudaGridDependencySynchronize();
#endif
    const int cnt = g_count;
    const int lane = threadIdx.x & 31;
    const int gw = (blockIdx.x * blockDim.x + threadIdx.x) >> 5;
    const int nwarps = (gridDim.x * blockDim.x) >> 5;

    for (int i = gw; i < cnt; i += nwarps) {
        const unsigned e = g_list[i];
        const unsigned pid = e >> 5;
        const int bit = (int)(e & 31u);
        const int kk = bit / 3;
        const int b  = bit % 3;
        const int dy = kk / 3 - 1, dx = kk % 3 - 1;
        const int n = (int)(pid >> 14);
        const int h = (int)((pid >> 7) & 127u);
        const int w = (int)(pid & 127u);

        const float* xp = x + (size_t)n * CIN * HW + (size_t)(h + dy) * WW + (w + dx);
        const float x0 = xp[(size_t)lane * HW];
        const float x1 = xp[(size_t)(lane + 32) * HW];

        const float2* wp = reinterpret_cast<const float2*>(
            g_wpack + (size_t)(b * 9 + kk) * (CIN * OUT)) + lane;

        float s0 = 0.0f, s1 = 0.0f;
        #pragma unroll
        for (int c = 0; c < 32; ++c) {
            const float xc = __shfl_sync(0xffffffffu, x0, c);
            const float2 wv = wp[c * 32];
            s0 = fmaf(wv.x, xc, s0);
            s1 = fmaf(wv.y, xc, s1);
        }
        #pragma unroll
        for (int c = 0; c < 32; ++c) {
            const float xc = __shfl_sync(0xffffffffu, x1, c);
            const float2 wv = wp[(c + 32) * 32];
            s0 = fmaf(wv.x, xc, s0);
            s1 = fmaf(wv.y, xc, s1);
        }

        float* op = out + (size_t)(n * OUT + 2 * lane) * HW + (size_t)h * WW + w;
        atomicAdd(op, s0);
        atomicAdd(op + HW, s1);
    }
}

// ============================================================
// launch (PDL: dense overlaps prep; correct overlaps dense tail)
// ============================================================
extern "C" void kernel_launch(void* const* d_in, const int* in_sizes, int n_in,
                              void* d_out, int out_size) {
    const float* x     = (const float*)d_in[0];
    const float* depth = (const float*)d_in[1];
    const float* fx    = (const float*)d_in[2];
    const float* w0    = (const float*)d_in[3];
    const float* w1    = (const float*)d_in[4];
    const float* w2    = (const float*)d_in[5];
    float* out = (float*)d_out;

    cudaFuncSetAttribute(k_dense_masks,
                         cudaFuncAttributeMaxDynamicSharedMemorySize, SM_TOTAL);

    k_prep<<<216, 128>>>(w0, w1, w2);

    cudaLaunchAttribute attr;
    attr.id = cudaLaunchAttributeProgrammaticStreamSerialization;
    attr.val.programmaticStreamSerializationAllowed = 1;

    {
        cudaLaunchConfig_t cfg = {};
        cfg.gridDim = dim3(NB * HH / 2);
        cfg.blockDim = dim3(256);
        cfg.dynamicSmemBytes = SM_TOTAL;
        cfg.stream = 0;
        cfg.attrs = &attr;
        cfg.numAttrs = 1;
        cudaLaunchKernelEx(&cfg, k_dense_masks, x, depth, fx, out);
    }
    {
        cudaLaunchConfig_t cfg = {};
        cfg.gridDim = dim3(128);
        cfg.blockDim = dim3(256);
        cfg.dynamicSmemBytes = 0;
        cfg.stream = 0;
        cfg.attrs = &attr;
        cfg.numAttrs = 1;
        cudaLaunchKernelEx(&cfg, k_correct, x, out);
    }
}

// round 17
// speedup vs baseline: 1.0495x; 1.0495x over previous
#include <cuda_runtime.h>
#include <cuda_bf16.h>
#include <cuda_fp16.h>
#include <cstdint>

#define NB   8
#define CIN  64
#define OUT  64
#define HH   128
#define WW   128
#define HW   (HH*WW)          // 16384
#define NPIX (NB*HW)          // 131072
#define KWSTRIDE 576
#define MAXENTRIES (NPIX * 24)

// -------- scratch (static __device__, no allocation) --------
__device__ int      g_count;
__device__ unsigned g_list[MAXENTRIES];         // overflow entries: pid<<5 | (kk*3+b)
__device__ float    g_wpack[3 * 9 * CIN * OUT]; // wpack[(b*9+kk)*4096 + c*64 + o]

// -------- smem layout for dense kernel (144B padded rows) ----
#define ROWB 144                   // 72 fp16 per row: 64 data + 8 pad
#define ROWE 72
#define SM_A    0
#define SM_B_H  (SM_A + 256 * ROWB)      // 36864
#define DS_STRIDE 132              // epilogue staging row stride (floats)
#define DS_FLOATS (OUT * DS_STRIDE)      // 8448 floats per image row
// list region disjoint from (A,B) during staging AND Ds during epilogue
#define SM_LCNT 67584
#define SM_LIST (SM_LCNT + 16)
#define LCAP    1024
#define SM_TOTAL (SM_LIST + LCAP * 4)    // 71696

// pre-converted dense B (w1 center taps), fp16, padded-row layout
__device__ __align__(16) __half g_bh[OUT * ROWE];

__device__ __forceinline__ uint32_t smem_u32(const void* p) {
    uint32_t a;
    asm("{ .reg .u64 t; cvta.to.shared.u64 t, %1; cvt.u32.u64 %0, t; }" : "=r"(a) : "l"(p));
    return a;
}
__device__ __forceinline__ void ldm_x4(uint32_t* r, uint32_t addr) {
    asm volatile("ldmatrix.sync.aligned.m8n8.x4.shared.b16 {%0,%1,%2,%3}, [%4];"
                 : "=r"(r[0]), "=r"(r[1]), "=r"(r[2]), "=r"(r[3]) : "r"(addr));
}
__device__ __forceinline__ void mma16816h(float* d, const uint32_t* a,
                                          uint32_t b0, uint32_t b1) {
    asm volatile(
        "mma.sync.aligned.m16n8k16.row.col.f32.f16.f16.f32 "
        "{%0,%1,%2,%3}, {%4,%5,%6,%7}, {%8,%9}, {%0,%1,%2,%3};"
        : "+f"(d[0]), "+f"(d[1]), "+f"(d[2]), "+f"(d[3])
        : "r"(a[0]), "r"(a[1]), "r"(a[2]), "r"(a[3]), "r"(b0), "r"(b1));
}

// non-center tap table: ki (0..7) -> kk (0..8, skipping 4)
__device__ __forceinline__ int ki_to_kk(int ki) { return ki < 4 ? ki : ki + 1; }

// ============================================================
// Kernel P: coalesced weight repack (PDL: triggers dense launch)
// ============================================================
__global__ void __launch_bounds__(128)
k_prep(const float* __restrict__ w0,
       const float* __restrict__ w1,
       const float* __restrict__ w2) {
#if __CUDA_ARCH__ >= 900
    cudaTriggerProgrammaticLaunchCompletion();
#endif
    if (blockIdx.x == 0 && threadIdx.x == 0) g_count = 0;

    const int tid = blockIdx.x * 128 + threadIdx.x;   // 0..27647
    const int b = tid / 9216;
    const int base = (tid % 9216) * 4;
    const float* wb = (b == 0) ? w0 : (b == 1) ? w1 : w2;

    const float4 v4 = *reinterpret_cast<const float4*>(wb + base);
    const float vv[4] = {v4.x, v4.y, v4.z, v4.w};

    #pragma unroll
    for (int j = 0; j < 4; ++j) {
        const int idx = base + j;                      // o*576 + c*9 + kk
        const float v = vv[j];
        const int o = idx / KWSTRIDE;
        const int rem = idx - o * KWSTRIDE;
        const int c = rem / 9;
        const int kk = rem - c * 9;
        g_wpack[(size_t)(b * 9 + kk) * (CIN * OUT) + c * OUT + o] = v;
        if (b == 1 && kk == 4)
            g_bh[o * ROWE + c] = __float2half_rn(v);
    }
}

// ============================================================
// Kernel A: FUSED dense (fp16 mma.sync, fp32 accum) + masks +
// corrections. Block = TWO image rows, 256 threads / 8 warps.
// Pre-sync phase (overlaps k_prep): A-staging + mask eval into
// a register bitmask. Post-sync: B copy, list pushes, MMA, etc.
// ============================================================
__global__ void __launch_bounds__(256, 2)
k_dense_masks(const float* __restrict__ x,
              const float* __restrict__ depth,
              const float* __restrict__ fx,
              float* __restrict__ out) {
    extern __shared__ char smem[];
    const uint32_t sb = smem_u32(smem);
    int* s_cnt = reinterpret_cast<int*>(smem + SM_LCNT);
    unsigned* slist = reinterpret_cast<unsigned*>(smem + SM_LIST);

    const int t = threadIdx.x;
    const int rg = t >> 7;
    const int tt = t & 127;
    const int wid = t >> 5, lane = t & 31;
    const int wl = wid & 3;
    const int n = blockIdx.x >> 6;
    const int hbase = (blockIdx.x & 63) << 1;
    const int h = hbase + rg;

    if (t == 0) *s_cnt = 0;

    // ---- pre-sync: stage A (x only), fp16, padded rows ----
    {
        const int q  = t & 63;           // pixel pair 0..63
        const int hf = (t >> 6) & 1;     // channel half
        const int rga = t >> 7;          // staging row
        const int px0 = q * 2;
        const float* xb = x + (size_t)n * CIN * HW +
                          (size_t)(hbase + rga) * WW + px0;
        char* a0 = smem + SM_A + (rga * 128 + px0) * ROWB;
        char* a1 = a0 + ROWB;

        #pragma unroll 8
        for (int c = hf * 32; c < hf * 32 + 32; c += 2) {
            const float2 f0 = *reinterpret_cast<const float2*>(xb + (size_t)c * HW);
            const float2 f1 = *reinterpret_cast<const float2*>(xb + (size_t)(c + 1) * HW);
            *reinterpret_cast<__half2*>(a0 + c * 2) =
                __float22half2_rn(make_float2(f0.x, f1.x));
            *reinterpret_cast<__half2*>(a1 + c * 2) =
                __float22half2_rn(make_float2(f0.y, f1.y));
        }
    }

    // ---- pre-sync: mask eval into register bitmask (depth/fx only) ----
    unsigned mbits = 0;
    {
        const int w = tt;
        const float* drow = depth + (size_t)n * HW;
        const float ctr = drow[h * WW + w];
        const float grid = ctr / fx[n];
        const float half = 0.5f * grid;
        const float t0 = ctr + grid;
        const float t2 = ctr - grid;
        #pragma unroll
        for (int ki = 0; ki < 8; ++ki) {
            const int kk = ki_to_kk(ki);
            const int dy = kk / 3 - 1, dx = kk % 3 - 1;
            const int hh = h + dy, ww2 = w + dx;
            if (hh < 0 || hh >= HH || ww2 < 0 || ww2 >= WW) continue;
            const float dv = drow[hh * WW + ww2];
            if (fabsf(dv - t0)  <= half) mbits |= 1u << (ki * 3 + 0);
            if (fabsf(dv - ctr) <= half) mbits |= 1u << (ki * 3 + 1);
            if (fabsf(dv - t2)  <= half) mbits |= 1u << (ki * 3 + 2);
        }
    }

    // ---- wait for k_prep's outputs (g_bh, g_wpack, g_count=0) ----
#if __CUDA_ARCH__ >= 900
    cudaGridDependencySynchronize();
#endif

    // ---- stage B: coalesced uint4 copy of fp16 weights (9216B) ----
    {
        const uint4* sh = reinterpret_cast<const uint4*>(g_bh);
        uint4* dh = reinterpret_cast<uint4*>(smem + SM_B_H);
        dh[t]       = sh[t];
        dh[t + 256] = sh[t + 256];
        if (t < 64) dh[t + 512] = sh[t + 512];
    }
    __syncthreads();   // also orders s_cnt=0 before pushes

    // ---- push deferred mask bits to block-local list ----
    {
        const unsigned pxloc = (unsigned)(rg * 128 + tt);
        const unsigned pid = (unsigned)(n * HW + h * WW + tt);
        unsigned mb = mbits;
        while (mb) {
            const int bit = __ffs(mb) - 1;
            mb &= mb - 1;
            const int ki = bit / 3, b = bit - ki * 3;
            const int kkb = ki_to_kk(ki) * 3 + b;
            const int pos = atomicAdd(s_cnt, 1);
            if (pos < LCAP) {
                slist[pos] = (pxloc << 5) | (unsigned)kkb;
            } else {
                const int gp = atomicAdd(&g_count, 1);
                g_list[gp] = (pid << 5) | (unsigned)kkb;
            }
        }
    }
#if __CUDA_ARCH__ >= 900
    cudaTriggerProgrammaticLaunchCompletion();
#endif

    // ---- MMA: 64 HMMA per warp (4 kt x 4 ntp x 2 mt x 2) ----
    const int g = lane >> 2;
    const int tig = lane & 3;
    const int px0 = wl * 32;

    const int amat = lane >> 3, ar = lane & 7;
    const uint32_t a_off = (uint32_t)((rg * 128 + px0 + ((amat & 1) << 3) + ar) * ROWB +
                                      (((amat >> 1) << 3) * 2));
    const uint32_t b_off = (uint32_t)(((((amat >> 1) << 3) + ar) * ROWB) +
                                      ((amat & 1) << 4));

    float acc[2][8][4];
    #pragma unroll
    for (int mt = 0; mt < 2; ++mt)
        #pragma unroll
        for (int nt = 0; nt < 8; ++nt)
            #pragma unroll
            for (int j = 0; j < 4; ++j) acc[mt][nt][j] = 0.0f;

    #pragma unroll
    for (int kt = 0; kt < 4; ++kt) {
        uint32_t ah[2][4];
        ldm_x4(ah[0], sb + SM_A + a_off + kt * 32);
        ldm_x4(ah[1], sb + SM_A + a_off + kt * 32 + 16 * ROWB);
        #pragma unroll
        for (int ntp = 0; ntp < 4; ++ntp) {
            uint32_t bh[4];
            ldm_x4(bh, sb + SM_B_H + b_off + ntp * 16 * ROWB + kt * 32);
            #pragma unroll
            for (int mt = 0; mt < 2; ++mt) {
                mma16816h(acc[mt][2 * ntp],     ah[mt], bh[0], bh[1]);
                mma16816h(acc[mt][2 * ntp + 1], ah[mt], bh[2], bh[3]);
            }
        }
    }

    // ---- transpose acc into smem staging (reuses A/B region) ----
    __syncthreads();           // A/B dead; list complete
    float* Ds = reinterpret_cast<float*>(smem) + rg * DS_FLOATS;
    #pragma unroll
    for (int mt = 0; mt < 2; ++mt) {
        #pragma unroll
        for (int nt = 0; nt < 8; ++nt) {
            const int o = nt * 8 + 2 * tig;
            const int px = px0 + mt * 16 + g;
            Ds[o * DS_STRIDE + px]           = acc[mt][nt][0];
            Ds[(o + 1) * DS_STRIDE + px]     = acc[mt][nt][1];
            Ds[o * DS_STRIDE + px + 8]       = acc[mt][nt][2];
            Ds[(o + 1) * DS_STRIDE + px + 8] = acc[mt][nt][3];
        }
    }
    __syncthreads();

    // ---- corrections: warps process the local list into Ds ----
    {
        const int cnt = min(*s_cnt, LCAP);
        for (int i = wid; i < cnt; i += 8) {
            const unsigned e = slist[i];
            const unsigned pxloc = e >> 5;
            const int bit = (int)(e & 31u);
            const int kk = bit / 3;
            const int b  = bit % 3;
            const int dy = kk / 3 - 1, dx = kk % 3 - 1;
            const int rg2 = (int)(pxloc >> 7);
            const int tt2 = (int)(pxloc & 127u);
            const int h2 = hbase + rg2;

            const float* xp = x + (size_t)n * CIN * HW +
                              (size_t)(h2 + dy) * WW + (tt2 + dx);
            const float x0 = xp[(size_t)lane * HW];
            const float x1 = xp[(size_t)(lane + 32) * HW];

            const float2* wp = reinterpret_cast<const float2*>(
                g_wpack + (size_t)(b * 9 + kk) * (CIN * OUT)) + lane;

            float s0 = 0.0f, s1 = 0.0f;
            #pragma unroll
            for (int c = 0; c < 32; ++c) {
                const float xc = __shfl_sync(0xffffffffu, x0, c);
                const float2 wv = wp[c * 32];
                s0 = fmaf(wv.x, xc, s0);
                s1 = fmaf(wv.y, xc, s1);
            }
            #pragma unroll
            for (int c = 0; c < 32; ++c) {
                const float xc = __shfl_sync(0xffffffffu, x1, c);
                const float2 wv = wp[(c + 32) * 32];
                s0 = fmaf(wv.x, xc, s0);
                s1 = fmaf(wv.y, xc, s1);
            }

            float* Dt = reinterpret_cast<float*>(smem) + rg2 * DS_FLOATS + tt2;
            atomicAdd(&Dt[(2 * lane) * DS_STRIDE],     s0);
            atomicAdd(&Dt[(2 * lane + 1) * DS_STRIDE], s1);
        }
    }
    __syncthreads();

    // ---- single coalesced float4 store: dense + corrections ----
    {
        const int p4 = (tt & 31) * 4;
        const int oph = tt >> 5;              // 0..3
        float* op = out + (size_t)(n * OUT) * HW + (size_t)h * WW + p4;
        #pragma unroll 4
        for (int o = oph; o < OUT; o += 4) {
            const float4 v = *reinterpret_cast<const float4*>(&Ds[o * DS_STRIDE + p4]);
            *reinterpret_cast<float4*>(op + (size_t)o * HW) = v;
        }
    }
}

// ============================================================
// Kernel C: overflow corrections (expected count = 0).
// ============================================================
__global__ void __launch_bounds__(256)
k_correct(const float* __restrict__ x,
          float* __restrict__ out) {
#if __CUDA_ARCH__ >= 900
    cudaGridDependencySynchronize();
#endif
    const int cnt = g_count;
    const int lane = threadIdx.x & 31;
    const int gw = (blockIdx.x * blockDim.x + threadIdx.x) >> 5;
    const int nwarps = (gridDim.x * blockDim.x) >> 5;

    for (int i = gw; i < cnt; i += nwarps) {
        const unsigned e = g_list[i];
        const unsigned pid = e >> 5;
        const int bit = (int)(e & 31u);
        const int kk = bit / 3;
        const int b  = bit % 3;
        const int dy = kk / 3 - 1, dx = kk % 3 - 1;
        const int n = (int)(pid >> 14);
        const int h = (int)((pid >> 7) & 127u);
        const int w = (int)(pid & 127u);

        const float* xp = x + (size_t)n * CIN * HW + (size_t)(h + dy) * WW + (w + dx);
        const float x0 = xp[(size_t)lane * HW];
        const float x1 = xp[(size_t)(lane + 32) * HW];

        const float2* wp = reinterpret_cast<const float2*>(
            g_wpack + (size_t)(b * 9 + kk) * (CIN * OUT)) + lane;

        float s0 = 0.0f, s1 = 0.0f;
        #pragma unroll
        for (int c = 0; c < 32; ++c) {
            const float xc = __shfl_sync(0xffffffffu, x0, c);
            const float2 wv = wp[c * 32];
            s0 = fmaf(wv.x, xc, s0);
            s1 = fmaf(wv.y, xc, s1);
        }
        #pragma unroll
        for (int c = 0; c < 32; ++c) {
            const float xc = __shfl_sync(0xffffffffu, x1, c);
            const float2 wv = wp[(c + 32) * 32];
            s0 = fmaf(wv.x, xc, s0);
            s1 = fmaf(wv.y, xc, s1);
        }

        float* op = out + (size_t)(n * OUT + 2 * lane) * HW + (size_t)h * WW + w;
        atomicAdd(op, s0);
        atomicAdd(op + HW, s1);
    }
}

// ============================================================
// launch (PDL: dense overlaps prep; correct overlaps dense tail)
// ============================================================
extern "C" void kernel_launch(void* const* d_in, const int* in_sizes, int n_in,
                              void* d_out, int out_size) {
    const float* x     = (const float*)d_in[0];
    const float* depth = (const float*)d_in[1];
    const float* fx    = (const float*)d_in[2];
    const float* w0    = (const float*)d_in[3];
    const float* w1    = (const float*)d_in[4];
    const float* w2    = (const float*)d_in[5];
    float* out = (float*)d_out;

    cudaFuncSetAttribute(k_dense_masks,
                         cudaFuncAttributeMaxDynamicSharedMemorySize, SM_TOTAL);

    k_prep<<<216, 128>>>(w0, w1, w2);

    cudaLaunchAttribute attr;
    attr.id = cudaLaunchAttributeProgrammaticStreamSerialization;
    attr.val.programmaticStreamSerializationAllowed = 1;

    {
        cudaLaunchConfig_t cfg = {};
        cfg.gridDim = dim3(NB * HH / 2);
        cfg.blockDim = dim3(256);
        cfg.dynamicSmemBytes = SM_TOTAL;
        cfg.stream = 0;
        cfg.attrs = &attr;
        cfg.numAttrs = 1;
        cudaLaunchKernelEx(&cfg, k_dense_masks, x, depth, fx, out);
    }
    {
        cudaLaunchConfig_t cfg = {};
        cfg.gridDim = dim3(128);
        cfg.blockDim = dim3(256);
        cfg.dynamicSmemBytes = 0;
        cfg.stream = 0;
        cfg.attrs = &attr;
        cfg.numAttrs = 1;
        cudaLaunchKernelEx(&cfg, k_correct, x, out);
    }
}